// round 16
// baseline (speedup 1.0000x reference)
#include <cuda_runtime.h>
#include <cuda_bf16.h>
#include <cstdint>

#define BB 2
#define CC 512
#define LQ 2048
#define LC 4096
#define HH 8
#define DD 64
#define BHH 16
#define TK 512
#define INNER 512

typedef unsigned long long ull;
typedef unsigned short u16;

// ---------------- packed f32x2 helpers ----------------
__device__ __forceinline__ void add2(ull& d, ull a, ull b) {
    asm("add.rn.f32x2 %0, %1, %2;" : "=l"(d) : "l"(a), "l"(b));
}
__device__ __forceinline__ float2 unpack2(ull v) {
    unsigned lo, hi;
    asm("mov.b64 {%0, %1}, %2;" : "=r"(lo), "=r"(hi) : "l"(v));
    return make_float2(__uint_as_float(lo), __uint_as_float(hi));
}

// ---------------- bf16 helpers ----------------
__device__ __forceinline__ u16 f2bf(float x) {
    __nv_bfloat16 b = __float2bfloat16(x);
    return *reinterpret_cast<u16*>(&b);
}
__device__ __forceinline__ float bf2f(u16 v) {
    __nv_bfloat16 b = *reinterpret_cast<__nv_bfloat16*>(&v);
    return __bfloat162float(b);
}
__device__ __forceinline__ void bsplit(float x, u16& h, u16& l) {
    h = f2bf(x);
    l = f2bf(x - bf2f(h));
}
__device__ __forceinline__ void mma_bf16(float* c, const uint32_t* a, const uint32_t* b) {
    asm volatile(
        "mma.sync.aligned.m16n8k16.row.col.f32.bf16.bf16.f32 "
        "{%0,%1,%2,%3}, {%4,%5,%6,%7}, {%8,%9}, {%0,%1,%2,%3};"
        : "+f"(c[0]), "+f"(c[1]), "+f"(c[2]), "+f"(c[3])
        : "r"(a[0]), "r"(a[1]), "r"(a[2]), "r"(a[3]), "r"(b[0]), "r"(b[1]));
}
__device__ __forceinline__ void ldsm4(uint32_t* r, uint32_t addr) {
    asm volatile("ldmatrix.sync.aligned.m8n8.x4.shared.b16 {%0,%1,%2,%3}, [%4];"
                 : "=r"(r[0]), "=r"(r[1]), "=r"(r[2]), "=r"(r[3]) : "r"(addr));
}
__device__ __forceinline__ void ldsm4t(uint32_t* r, uint32_t addr) {
    asm volatile("ldmatrix.sync.aligned.m8n8.x4.trans.shared.b16 {%0,%1,%2,%3}, [%4];"
                 : "=r"(r[0]), "=r"(r[1]), "=r"(r[2]), "=r"(r[3]) : "r"(addr));
}
__device__ __forceinline__ uint32_t smem_u32(const void* p) {
    uint32_t a;
    asm("{ .reg .u64 t; cvta.to.shared.u64 t, %1; cvt.u32.u64 %0, t; }" : "=r"(a) : "l"(p));
    return a;
}
__device__ __forceinline__ void cpa16(uint32_t s, const void* g) {
    asm volatile("cp.async.cg.shared.global [%0], [%1], 16;" :: "r"(s), "l"(g));
}

// ---------------- scratch ----------------
__device__ u16 g_ctxh[BB * LC * CC];
__device__ u16 g_ctxl[BB * LC * CC];
__device__ u16 g_qsh[BB * LQ * CC];
__device__ u16 g_qsl[BB * LQ * CC];
__device__ u16 g_wkvh[1024 * CC];
__device__ u16 g_wkvl[1024 * CC];
__device__ u16 g_wqh[INNER * CC];
__device__ u16 g_wql[INNER * CC];
__device__ u16 g_woh[CC * INNER];
__device__ u16 g_wol[CC * INNER];
__device__ u16 g_aoh[BB * LQ * INNER];
__device__ u16 g_aol[BB * LQ * INNER];
__device__ float g_dkv[BB * LC * 2 * INNER];
__device__ float g_dq[BB * LQ * INNER];
__device__ float g_dout[BB * LQ * CC];
__device__ float g_qsm[BHH * TK * DD];
__device__ float g_mind[BHH * LC];
__device__ int g_sidx[BHH * TK];
__device__ u16 g_kselh[BHH * TK * DD];
__device__ u16 g_ksell[BHH * TK * DD];
__device__ u16 g_vselh[BHH * TK * DD];
__device__ u16 g_vsell[BHH * TK * DD];

// ---------------- Threefry (host + device) ----------------
__host__ __device__ __forceinline__ void tf2x32(unsigned k0, unsigned k1, unsigned x0,
                                                unsigned x1, unsigned& y0, unsigned& y1) {
    unsigned ks2 = k0 ^ k1 ^ 0x1BD11BDAu;
    x0 += k0; x1 += k1;
#define TFR(r) { x0 += x1; x1 = (x1 << (r)) | (x1 >> (32 - (r))); x1 ^= x0; }
    TFR(13) TFR(15) TFR(26) TFR(6)
    x0 += k1; x1 += ks2 + 1u;
    TFR(17) TFR(29) TFR(16) TFR(24)
    x0 += ks2; x1 += k0 + 2u;
    TFR(13) TFR(15) TFR(26) TFR(6)
    x0 += k0; x1 += k1 + 3u;
    TFR(17) TFR(29) TFR(16) TFR(24)
    x0 += k1; x1 += ks2 + 4u;
    TFR(13) TFR(15) TFR(26) TFR(6)
    x0 += ks2; x1 += k0 + 5u;
#undef TFR
    y0 = x0; y1 = x1;
}

// ---------------- weight bf16 hi/lo split ----------------
__global__ void split_kernel(const float* __restrict__ src, u16* __restrict__ hi,
                             u16* __restrict__ lo, int n) {
    int i = blockIdx.x * 256 + threadIdx.x;
    if (i >= n) return;
    u16 h, l;
    bsplit(src[i], h, l);
    hi[i] = h;
    lo[i] = l;
}

// ---------------- ChanLN: x (b,C,L) -> bf16 hi/lo (b,L,C) ----------------
__global__ void chan_ln_t(const float* __restrict__ x, const float* __restrict__ gw,
                          const float* __restrict__ bw, u16* __restrict__ yh,
                          u16* __restrict__ yl, int L) {
    int b = blockIdx.y;
    int l0 = blockIdx.x * 32;
    int lane = threadIdx.x, wy = threadIdx.y;
    const float* xb = x + (size_t)b * CC * L;
    float s = 0.f, s2 = 0.f;
    for (int c = wy; c < CC; c += 8) {
        float v = xb[(size_t)c * L + l0 + lane];
        s += v; s2 += v * v;
    }
    __shared__ float sh_s[8][32], sh_s2[8][32];
    __shared__ float mean_s[32], rstd_s[32];
    __shared__ float tile[32][33];
    sh_s[wy][lane] = s; sh_s2[wy][lane] = s2;
    __syncthreads();
    if (wy == 0) {
        float ts = 0.f, t2 = 0.f;
        #pragma unroll
        for (int i = 0; i < 8; i++) { ts += sh_s[i][lane]; t2 += sh_s2[i][lane]; }
        float mean = ts / (float)CC;
        float var = t2 / (float)CC - mean * mean;
        mean_s[lane] = mean;
        rstd_s[lane] = rsqrtf(var + 1e-5f);
    }
    __syncthreads();
    u16* yhb = yh + (size_t)b * L * CC;
    u16* ylb = yl + (size_t)b * L * CC;
    for (int c0 = 0; c0 < CC; c0 += 32) {
        #pragma unroll
        for (int rr = 0; rr < 4; rr++) {
            int cr = wy * 4 + rr;
            tile[cr][lane] = xb[(size_t)(c0 + cr) * L + l0 + lane];
        }
        __syncthreads();
        #pragma unroll
        for (int rr = 0; rr < 4; rr++) {
            int r = wy * 4 + rr;
            int c = c0 + lane;
            float v = tile[lane][r];
            float o = (v - mean_s[r]) * rstd_s[r] * gw[c] + bw[c];
            u16 h, l;
            bsplit(o, h, l);
            yhb[(size_t)(l0 + r) * CC + c] = h;
            ylb[(size_t)(l0 + r) * CC + c] = l;
        }
        __syncthreads();
    }
}

// ---------------- final LN ----------------
__global__ void final_ln_t(const float* __restrict__ x, const float* __restrict__ gw,
                           const float* __restrict__ bw, const float* __restrict__ res,
                           const float* __restrict__ gamma, float* __restrict__ y) {
    int b = blockIdx.y;
    int l0 = blockIdx.x * 32;
    int lane = threadIdx.x, wy = threadIdx.y;
    const float* xb = x + (size_t)b * LQ * CC;
    __shared__ float mean_s[32], rstd_s[32];
    __shared__ float tile[32][33];
    #pragma unroll
    for (int rr = 0; rr < 4; rr++) {
        int r = wy * 4 + rr;
        const float* row = xb + (size_t)(l0 + r) * CC;
        float s = 0.f, s2 = 0.f;
        for (int c = lane; c < CC; c += 32) { float v = row[c]; s += v; s2 += v * v; }
        #pragma unroll
        for (int o = 16; o > 0; o >>= 1) {
            s += __shfl_xor_sync(0xFFFFFFFFu, s, o);
            s2 += __shfl_xor_sync(0xFFFFFFFFu, s2, o);
        }
        if (lane == 0) {
            float mean = s / (float)CC;
            float var = s2 / (float)CC - mean * mean;
            mean_s[r] = mean;
            rstd_s[r] = rsqrtf(var + 1e-5f);
        }
    }
    __syncthreads();
    float gm = gamma[0];
    const float* rb = res + (size_t)b * CC * LQ;
    float* yb = y + (size_t)b * CC * LQ;
    for (int c0 = 0; c0 < CC; c0 += 32) {
        #pragma unroll
        for (int rr = 0; rr < 4; rr++) {
            int r = wy * 4 + rr;
            tile[r][lane] = xb[(size_t)(l0 + r) * CC + c0 + lane];
        }
        __syncthreads();
        #pragma unroll
        for (int rr = 0; rr < 4; rr++) {
            int cr = wy * 4 + rr;
            int c = c0 + cr;
            float v = tile[lane][cr];
            float o = gm * ((v - mean_s[lane]) * rstd_s[lane] * gw[c] + bw[c])
                      + rb[(size_t)c * LQ + l0 + lane];
            yb[(size_t)c * LQ + l0 + lane] = o;
        }
        __syncthreads();
    }
}

// ---------------- pipelined 3xBF16 GEMM (ldmatrix frags) + fused L2-norm epilogue ----------------
#define KCW 32
#define LDAU 20
#define TSZ (128 * LDAU)
__global__ void __launch_bounds__(256, 2) mma_bf3_gemm(const u16* __restrict__ Xh,
                                                       const u16* __restrict__ Xl,
                                                       const u16* __restrict__ Wh,
                                                       const u16* __restrict__ Wl,
                                                       float* __restrict__ Dout, int Ncols,
                                                       size_t xStride, size_t dStride,
                                                       int normMode, int bnOff) {
    extern __shared__ uint32_t sm[];
    uint32_t* Ah = sm;
    uint32_t* Al = sm + 2 * TSZ;
    uint32_t* Bh = sm + 4 * TSZ;
    uint32_t* Bl = sm + 6 * TSZ;
    int tid = threadIdx.x;
    int warp = tid >> 5, lane = tid & 31;
    int wm = warp & 1, wn = warp >> 1;
    int g = lane >> 2, t = lane & 3;
    int bn = blockIdx.x * 128 + bnOff, bm = blockIdx.y * 128, b = blockIdx.z;
    const u16* Xbh = Xh + (size_t)b * xStride;
    const u16* Xbl = Xl + (size_t)b * xStride;
    float* Db = Dout + (size_t)b * dStride;
    int emode = (normMode == 1 && bn >= 512) ? 0 : normMode;

    float acc[4][4][4];
    #pragma unroll
    for (int i = 0; i < 4; i++)
        #pragma unroll
        for (int j = 0; j < 4; j++)
            #pragma unroll
            for (int e = 0; e < 4; e++) acc[i][j][e] = 0.f;

    int lrow = tid >> 2;
    int lchk = tid & 3;

    auto load_stage = [&](int buf, int k0) {
        #pragma unroll
        for (int p = 0; p < 2; p++) {
            int row = p * 64 + lrow;
            size_t go = (size_t)(bm + row) * CC + k0 + lchk * 8;
            size_t gw = (size_t)(bn + row) * CC + k0 + lchk * 8;
            uint32_t so = (uint32_t)(buf * TSZ + row * LDAU + lchk * 4) * 4u;
            cpa16(smem_u32(Ah) + so, Xbh + go);
            cpa16(smem_u32(Al) + so, Xbl + go);
            cpa16(smem_u32(Bh) + so, Wh + gw);
            cpa16(smem_u32(Bl) + so, Wl + gw);
        }
        asm volatile("cp.async.commit_group;" ::: "memory");
    };

    int lsel = lane & 15, khalf = lane >> 4;
    uint32_t aoff[4];
    #pragma unroll
    for (int mt = 0; mt < 4; mt++)
        aoff[mt] = (uint32_t)(((wm * 64 + mt * 16 + lsel) * LDAU + khalf * 4) * 4);
    int bseg = lane >> 3, brow = lane & 7;
    uint32_t boff[2];
    #pragma unroll
    for (int np = 0; np < 2; np++)
        boff[np] = (uint32_t)(((wn * 32 + (np * 2 + (bseg >> 1)) * 8 + brow) * LDAU
                               + (bseg & 1) * 4) * 4);
    uint32_t aBaseH = smem_u32(Ah), aBaseL = smem_u32(Al);
    uint32_t bBaseH = smem_u32(Bh), bBaseL = smem_u32(Bl);

    const int NST = CC / KCW;
    load_stage(0, 0);
    for (int st = 0; st < NST; st++) {
        if (st + 1 < NST) {
            load_stage((st + 1) & 1, (st + 1) * KCW);
            asm volatile("cp.async.wait_group 1;" ::: "memory");
        } else {
            asm volatile("cp.async.wait_group 0;" ::: "memory");
        }
        __syncthreads();
        int buf = st & 1;
        #pragma unroll
        for (int ks = 0; ks < 2; ks++) {
            uint32_t kso = (uint32_t)((buf * TSZ + ks * 8) * 4);
            uint32_t bh4[2][4], bl4[2][4];
            ldsm4(bh4[0], bBaseH + boff[0] + kso);
            ldsm4(bh4[1], bBaseH + boff[1] + kso);
            ldsm4(bl4[0], bBaseL + boff[0] + kso);
            ldsm4(bl4[1], bBaseL + boff[1] + kso);
            #pragma unroll
            for (int mt = 0; mt < 4; mt++) {
                uint32_t ah[4], al[4];
                ldsm4(ah, aBaseH + aoff[mt] + kso);
                ldsm4(al, aBaseL + aoff[mt] + kso);
                #pragma unroll
                for (int nt = 0; nt < 4; nt++) {
                    uint32_t bhi[2] = {bh4[nt >> 1][(nt & 1) * 2], bh4[nt >> 1][(nt & 1) * 2 + 1]};
                    uint32_t blo[2] = {bl4[nt >> 1][(nt & 1) * 2], bl4[nt >> 1][(nt & 1) * 2 + 1]};
                    mma_bf16(acc[mt][nt], ah, bhi);
                    mma_bf16(acc[mt][nt], ah, blo);
                    mma_bf16(acc[mt][nt], al, bhi);
                }
            }
        }
        __syncthreads();
    }

    float* ns = reinterpret_cast<float*>(sm);
    int hh = wn >> 1;
    if (emode != 0) {
        for (int i = tid; i < 256; i += 256) ns[i] = 0.f;
        __syncthreads();
        #pragma unroll
        for (int mt = 0; mt < 4; mt++) {
            float p0 = 0.f, p1 = 0.f;
            #pragma unroll
            for (int nt = 0; nt < 4; nt++) {
                p0 += acc[mt][nt][0] * acc[mt][nt][0] + acc[mt][nt][1] * acc[mt][nt][1];
                p1 += acc[mt][nt][2] * acc[mt][nt][2] + acc[mt][nt][3] * acc[mt][nt][3];
            }
            int r0 = wm * 64 + mt * 16 + g;
            atomicAdd(&ns[r0 * 2 + hh], p0);
            atomicAdd(&ns[(r0 + 8) * 2 + hh], p1);
        }
        __syncthreads();
    }
    bool donorm = (emode == 2) || (emode == 1 && (bn + wn * 32) < 512);
    #pragma unroll
    for (int mt = 0; mt < 4; mt++) {
        int rl = wm * 64 + mt * 16 + g;
        float inv0 = 1.f, inv1 = 1.f;
        if (donorm) {
            inv0 = 1.f / fmaxf(sqrtf(ns[rl * 2 + hh]), 1e-12f);
            inv1 = 1.f / fmaxf(sqrtf(ns[(rl + 8) * 2 + hh]), 1e-12f);
        }
        int r0 = bm + rl;
        #pragma unroll
        for (int nt = 0; nt < 4; nt++) {
            int c0 = bn + wn * 32 + nt * 8 + t * 2;
            *reinterpret_cast<float2*>(&Db[(size_t)r0 * Ncols + c0]) =
                make_float2(acc[mt][nt][0] * inv0, acc[mt][nt][1] * inv0);
            *reinterpret_cast<float2*>(&Db[(size_t)(r0 + 8) * Ncols + c0]) =
                make_float2(acc[mt][nt][2] * inv1, acc[mt][nt][3] * inv1);
        }
    }
}

// ---------------- gathers ----------------
__global__ void gather_qsmall(unsigned k2a, unsigned k2b) {
    int r = blockIdx.x * 8 + threadIdx.y;
    int bh = r >> 9;
    int b = bh >> 3, h = bh & 7;
    unsigned y0, y1;
    tf2x32(k2a, k2b, 0u, (unsigned)r, y0, y1);
    int idx = (int)((y0 ^ y1) & 2047u);
    const float* s = g_dq + ((size_t)b * LQ + idx) * INNER + h * DD;
    float* d = g_qsm + (size_t)r * DD;
    d[threadIdx.x] = s[threadIdx.x];
    d[threadIdx.x + 32] = s[threadIdx.x + 32];
}

// gather selected K and V as bf16 hi/lo (rOff = bhOff*TK)
__global__ void gather_sel(int rOff) {
    int r = rOff + blockIdx.x * 8 + threadIdx.y;
    int bh = r >> 9;
    int b = bh >> 3, h = bh & 7;
    int idx = g_sidx[r];
    const float* ks = g_dkv + ((size_t)b * LC + idx) * (2 * INNER) + h * DD;
    #pragma unroll
    for (int p = 0; p < 2; p++) {
        int c = threadIdx.x + p * 32;
        u16 hh_, ll_;
        bsplit(ks[c], hh_, ll_);
        g_kselh[(size_t)r * DD + c] = hh_;
        g_ksell[(size_t)r * DD + c] = ll_;
        bsplit(ks[INNER + c], hh_, ll_);
        g_vselh[(size_t)r * DD + c] = hh_;
        g_vsell[(size_t)r * DD + c] = ll_;
    }
}

// ---------------- L1 min-distance (per-half via bhOff) ----------------
__global__ void __launch_bounds__(256, 2) l1_min_kernel(int bhOff) {
    int bh = blockIdx.y + bhOff;
    int b = bh >> 3, h = bh & 7;
    int kl = blockIdx.x * 256 + threadIdx.x;
    const ull* kp = reinterpret_cast<const ull*>(g_dkv + ((size_t)b * LC + kl) * (2 * INNER) + h * DD);
    ull kr2[32];
    #pragma unroll
    for (int i = 0; i < 32; i++) kr2[i] = kp[i];
    __shared__ float qs[128 * 64];
    const ull ABSM = 0x7FFFFFFF7FFFFFFFull;
    float best = 3.4e38f;
    for (int qc = 0; qc < TK; qc += 128) {
        const float4* qsrc4 = reinterpret_cast<const float4*>(g_qsm + ((size_t)bh * TK + qc) * DD);
        for (int j = threadIdx.x; j < 128 * 16; j += 256) {
            float4 v = qsrc4[j];
            reinterpret_cast<float4*>(qs)[j] = make_float4(-v.x, -v.y, -v.z, -v.w);
        }
        __syncthreads();
        for (int qq = 0; qq < 128; qq++) {
            const ull* qp = reinterpret_cast<const ull*>(qs + qq * 64);
            ull a0 = 0ull, a1 = 0ull, a2 = 0ull, a3 = 0ull;
            #pragma unroll
            for (int i = 0; i < 32; i += 4) {
                ull d0, d1, d2, d3;
                add2(d0, kr2[i + 0], qp[i + 0]); d0 &= ABSM; add2(a0, a0, d0);
                add2(d1, kr2[i + 1], qp[i + 1]); d1 &= ABSM; add2(a1, a1, d1);
                add2(d2, kr2[i + 2], qp[i + 2]); d2 &= ABSM; add2(a2, a2, d2);
                add2(d3, kr2[i + 3], qp[i + 3]); d3 &= ABSM; add2(a3, a3, d3);
            }
            ull s01, s23, s;
            add2(s01, a0, a1);
            add2(s23, a2, a3);
            add2(s, s01, s23);
            float2 f = unpack2(s);
            best = fminf(best, f.x + f.y);
        }
        __syncthreads();
    }
    g_mind[(size_t)bh * LC + kl] = best;
}

// ---------------- top-512 smallest via bitonic sort (per-half) ----------------
__global__ void __launch_bounds__(1024) topk_kernel(int bhOff) {
    __shared__ ull keys[LC];
    int bh = blockIdx.x + bhOff;
    int tid = threadIdx.x;
    for (int i = tid; i < LC; i += 1024) {
        unsigned fb = __float_as_uint(g_mind[(size_t)bh * LC + i]);
        keys[i] = ((ull)fb << 32) | (unsigned)i;
    }
    __syncthreads();
    for (int k = 2; k <= LC; k <<= 1) {
        for (int j = k >> 1; j > 0; j >>= 1) {
            for (int i = tid; i < LC; i += 1024) {
                int ixj = i ^ j;
                if (ixj > i) {
                    ull a = keys[i], bb = keys[ixj];
                    bool up = ((i & k) == 0);
                    if ((a > bb) == up) { keys[i] = bb; keys[ixj] = a; }
                }
            }
            __syncthreads();
        }
    }
    for (int i = tid; i < TK; i += 1024)
        g_sidx[bh * TK + i] = (int)(keys[i] & 0xFFFFFFFFu);
}

// ---------------- flash attention on bf16 mma (per-half via bhOff) ----------------
#define LDS2 72
__global__ void __launch_bounds__(256) attn_mma(int bhOff) {
    __shared__ u16 smA[128 * LDS2];
    __shared__ u16 smB[128 * LDS2];
    int bh = blockIdx.y + bhOff;
    int b = bh >> 3, h = bh & 7;
    int bm = blockIdx.x * 128;
    int tid = threadIdx.x, w = tid >> 5, lane = tid & 31;
    int g = lane >> 2, t = lane & 3;

    for (int i = tid; i < 128 * 64; i += 256) {
        int row = i >> 6, c = i & 63;
        float v = g_dq[((size_t)b * LQ + bm + row) * INNER + h * DD + c];
        u16 hh_, ll_;
        bsplit(v, hh_, ll_);
        smA[row * LDS2 + c] = hh_;
        smB[row * LDS2 + c] = ll_;
    }
    __syncthreads();

    uint32_t qh[4][4], ql[4][4];
    int arow = lane & 15, ahalf = lane >> 4;
    #pragma unroll
    for (int ks = 0; ks < 4; ks++) {
        ldsm4(qh[ks], smem_u32(&smA[(w * 16 + arow) * LDS2 + ks * 16 + ahalf * 8]));
        ldsm4(ql[ks], smem_u32(&smB[(w * 16 + arow) * LDS2 + ks * 16 + ahalf * 8]));
    }
    __syncthreads();

    u16* Kh = smA;
    u16* Kl = smA + 64 * LDS2;
    u16* Vh = smB;
    u16* Vl = smB + 64 * LDS2;

    float O[8][4];
    #pragma unroll
    for (int i = 0; i < 8; i++)
        #pragma unroll
        for (int e = 0; e < 4; e++) O[i][e] = 0.f;
    float den0 = 0.f, den1 = 0.f;

    int brow = ((lane >> 4) << 3) + (lane & 7);
    int bhalf = (lane >> 3) & 1;
    int vrow = ((lane >> 3) & 1) * 8 + (lane & 7);
    int vch = lane >> 4;

    for (int kc = 0; kc < TK; kc += 64) {
        for (int j = tid; j < 512; j += 256) {
            int row = j >> 3, seg = j & 7;
            size_t src = ((size_t)bh * TK + kc + row) * DD + seg * 8;
            uint32_t dst = (uint32_t)(row * LDS2 + seg * 8) * 2u;
            cpa16(smem_u32(Kh) + dst, g_kselh + src);
            cpa16(smem_u32(Kl) + dst, g_ksell + src);
            cpa16(smem_u32(Vh) + dst, g_vselh + src);
            cpa16(smem_u32(Vl) + dst, g_vsell + src);
        }
        asm volatile("cp.async.commit_group;" ::: "memory");
        asm volatile("cp.async.wait_group 0;" ::: "memory");
        __syncthreads();

        float S[8][4];
        #pragma unroll
        for (int i = 0; i < 8; i++)
            #pragma unroll
            for (int e = 0; e < 4; e++) S[i][e] = 0.f;
        #pragma unroll
        for (int ks = 0; ks < 4; ks++) {
            #pragma unroll
            for (int pr = 0; pr < 4; pr++) {
                uint32_t kh4[4], kl4[4];
                uint32_t ko = (uint32_t)((pr * 16 + brow) * LDS2 + ks * 16 + bhalf * 8) * 2u;
                ldsm4(kh4, smem_u32(Kh) + ko);
                ldsm4(kl4, smem_u32(Kl) + ko);
                #pragma unroll
                for (int sub = 0; sub < 2; sub++) {
                    int nt = pr * 2 + sub;
                    uint32_t bhr[2] = {kh4[sub * 2], kh4[sub * 2 + 1]};
                    uint32_t blr[2] = {kl4[sub * 2], kl4[sub * 2 + 1]};
                    mma_bf16(S[nt], qh[ks], bhr);
                    mma_bf16(S[nt], qh[ks], blr);
                    mma_bf16(S[nt], ql[ks], bhr);
                }
            }
        }

        #pragma unroll
        for (int ks = 0; ks < 4; ks++) {
            uint32_t prh[4], prl[4];
            #pragma unroll
            for (int half = 0; half < 2; half++) {
                int nt = 2 * ks + half;
                #pragma unroll
                for (int pe = 0; pe < 2; pe++) {
                    float w0 = __expf(S[nt][pe * 2]);
                    float w1 = __expf(S[nt][pe * 2 + 1]);
                    u16 h0, l0, h1, l1;
                    bsplit(w0, h0, l0);
                    bsplit(w1, h1, l1);
                    prh[half * 2 + pe] = (uint32_t)h0 | ((uint32_t)h1 << 16);
                    prl[half * 2 + pe] = (uint32_t)l0 | ((uint32_t)l1 << 16);
                    float wr0 = bf2f(h0) + bf2f(l0);
                    float wr1 = bf2f(h1) + bf2f(l1);
                    if (pe == 0) den0 += wr0 + wr1; else den1 += wr0 + wr1;
                }
            }
            #pragma unroll
            for (int vp = 0; vp < 4; vp++) {
                uint32_t vh4[4], vl4[4];
                uint32_t vo = (uint32_t)((ks * 16 + vrow) * LDS2 + vp * 16 + vch * 8) * 2u;
                ldsm4t(vh4, smem_u32(Vh) + vo);
                ldsm4t(vl4, smem_u32(Vl) + vo);
                #pragma unroll
                for (int sub = 0; sub < 2; sub++) {
                    uint32_t vbh[2] = {vh4[sub * 2], vh4[sub * 2 + 1]};
                    uint32_t vbl[2] = {vl4[sub * 2], vl4[sub * 2 + 1]};
                    mma_bf16(O[vp * 2 + sub], prh, vbh);
                    mma_bf16(O[vp * 2 + sub], prh, vbl);
                    mma_bf16(O[vp * 2 + sub], prl, vbh);
                }
            }
        }
        __syncthreads();
    }

    den0 += __shfl_xor_sync(0xFFFFFFFFu, den0, 1);
    den0 += __shfl_xor_sync(0xFFFFFFFFu, den0, 2);
    den1 += __shfl_xor_sync(0xFFFFFFFFu, den1, 1);
    den1 += __shfl_xor_sync(0xFFFFFFFFu, den1, 2);
    float inv0 = 1.f / den0, inv1 = 1.f / den1;

    int row0 = bm + w * 16 + g;
    #pragma unroll
    for (int nt = 0; nt < 8; nt++) {
        int col = h * DD + nt * 8 + t * 2;
        float o0 = O[nt][0] * inv0, o1 = O[nt][1] * inv0;
        float o2 = O[nt][2] * inv1, o3 = O[nt][3] * inv1;
        u16 h0, l0, h1, l1, h2, l2, h3, l3;
        bsplit(o0, h0, l0); bsplit(o1, h1, l1);
        bsplit(o2, h2, l2); bsplit(o3, h3, l3);
        size_t i0 = ((size_t)b * LQ + row0) * INNER + col;
        size_t i1 = ((size_t)b * LQ + row0 + 8) * INNER + col;
        *reinterpret_cast<uint32_t*>(g_aoh + i0) = (uint32_t)h0 | ((uint32_t)h1 << 16);
        *reinterpret_cast<uint32_t*>(g_aol + i0) = (uint32_t)l0 | ((uint32_t)l1 << 16);
        *reinterpret_cast<uint32_t*>(g_aoh + i1) = (uint32_t)h2 | ((uint32_t)h3 << 16);
        *reinterpret_cast<uint32_t*>(g_aol + i1) = (uint32_t)l2 | ((uint32_t)l3 << 16);
    }
}

// ---------------- streams/events (static init; no device memory) ----------------
struct StreamPack {
    cudaStream_t sB, sC;
    cudaEvent_t evRoot, evB, evC, evC2, evLn, evV, evL0, evA0;
    StreamPack() {
        cudaStreamCreateWithFlags(&sB, cudaStreamNonBlocking);
        cudaStreamCreateWithFlags(&sC, cudaStreamNonBlocking);
        cudaEventCreateWithFlags(&evRoot, cudaEventDisableTiming);
        cudaEventCreateWithFlags(&evB, cudaEventDisableTiming);
        cudaEventCreateWithFlags(&evC, cudaEventDisableTiming);
        cudaEventCreateWithFlags(&evC2, cudaEventDisableTiming);
        cudaEventCreateWithFlags(&evLn, cudaEventDisableTiming);
        cudaEventCreateWithFlags(&evV, cudaEventDisableTiming);
        cudaEventCreateWithFlags(&evL0, cudaEventDisableTiming);
        cudaEventCreateWithFlags(&evA0, cudaEventDisableTiming);
    }
};
static StreamPack g_sp;

// ---------------- host ----------------
extern "C" void kernel_launch(void* const* d_in, const int* in_sizes, int n_in,
                              void* d_out, int out_size) {
    (void)in_sizes; (void)n_in; (void)out_size;
    const float* qsrc  = (const float*)d_in[0];
    const float* ctx   = (const float*)d_in[1];
    const float* cn_g  = (const float*)d_in[2];
    const float* cn_b  = (const float*)d_in[3];
    const float* qn_g  = (const float*)d_in[4];
    const float* qn_b  = (const float*)d_in[5];
    const float* on_g  = (const float*)d_in[6];
    const float* on_b  = (const float*)d_in[7];
    const float* w_kv  = (const float*)d_in[8];
    const float* w_q   = (const float*)d_in[9];
    const float* w_out = (const float*)d_in[10];
    const float* gamma = (const float*)d_in[11];
    float* out = (float*)d_out;

    u16 *p_ctxh, *p_ctxl, *p_qsh, *p_qsl, *p_wkvh, *p_wkvl, *p_wqh, *p_wql,
        *p_woh, *p_wol, *p_aoh, *p_aol;
    float *p_dkv, *p_dq, *p_dout;
    cudaGetSymbolAddress((void**)&p_ctxh, g_ctxh);
    cudaGetSymbolAddress((void**)&p_ctxl, g_ctxl);
    cudaGetSymbolAddress((void**)&p_qsh, g_qsh);
    cudaGetSymbolAddress((void**)&p_qsl, g_qsl);
    cudaGetSymbolAddress((void**)&p_wkvh, g_wkvh);
    cudaGetSymbolAddress((void**)&p_wkvl, g_wkvl);
    cudaGetSymbolAddress((void**)&p_wqh, g_wqh);
    cudaGetSymbolAddress((void**)&p_wql, g_wql);
    cudaGetSymbolAddress((void**)&p_woh, g_woh);
    cudaGetSymbolAddress((void**)&p_wol, g_wol);
    cudaGetSymbolAddress((void**)&p_aoh, g_aoh);
    cudaGetSymbolAddress((void**)&p_aol, g_aol);
    cudaGetSymbolAddress((void**)&p_dkv, g_dkv);
    cudaGetSymbolAddress((void**)&p_dq, g_dq);
    cudaGetSymbolAddress((void**)&p_dout, g_dout);

    unsigned k2a, k2b;
    tf2x32(0u, 42u, 0u, 1u, k2a, k2b);

    const int GEMM_SMEM = 8 * TSZ * 4;  // 81920 bytes -> 2 CTAs/SM
    cudaFuncSetAttribute(mma_bf3_gemm, cudaFuncAttributeMaxDynamicSharedMemorySize, GEMM_SMEM);

    dim3 thr328(32, 8);

    // ---- fork ----
    cudaEventRecord(g_sp.evRoot, 0);
    cudaStreamWaitEvent(g_sp.sB, g_sp.evRoot, 0);
    cudaStreamWaitEvent(g_sp.sC, g_sp.evRoot, 0);

    // stream C: wkv split
    split_kernel<<<(1024 * CC) / 256, 256, 0, g_sp.sC>>>(w_kv, p_wkvh, p_wkvl, 1024 * CC);
    cudaEventRecord(g_sp.evC, g_sp.sC);

    // stream B: q path
    chan_ln_t<<<dim3(LQ / 32, BB), thr328, 0, g_sp.sB>>>(qsrc, qn_g, qn_b, p_qsh, p_qsl, LQ);
    split_kernel<<<(INNER * CC) / 256, 256, 0, g_sp.sB>>>(w_q, p_wqh, p_wql, INNER * CC);
    mma_bf3_gemm<<<dim3(INNER / 128, LQ / 128, BB), 256, GEMM_SMEM, g_sp.sB>>>(
        p_qsh, p_qsl, p_wqh, p_wql, p_dq, INNER, (size_t)LQ * CC, (size_t)LQ * INNER, 2, 0);
    gather_qsmall<<<BHH * TK / 8, thr328, 0, g_sp.sB>>>(k2a, k2b);
    cudaEventRecord(g_sp.evB, g_sp.sB);

    // main: ctx LN -> k-GEMM (cols 0-511)
    chan_ln_t<<<dim3(LC / 32, BB), thr328>>>(ctx, cn_g, cn_b, p_ctxh, p_ctxl, LC);
    cudaEventRecord(g_sp.evLn, 0);
    cudaStreamWaitEvent(0, g_sp.evC, 0);
    mma_bf3_gemm<<<dim3(512 / 128, LC / 128, BB), 256, GEMM_SMEM>>>(
        p_ctxh, p_ctxl, p_wkvh, p_wkvl, p_dkv, 1024, (size_t)LC * CC, (size_t)LC * 1024, 1, 0);

    // stream C: v-GEMM (cols 512-1023), overlaps l1(h0); then wout split
    cudaStreamWaitEvent(g_sp.sC, g_sp.evLn, 0);
    mma_bf3_gemm<<<dim3(512 / 128, LC / 128, BB), 256, GEMM_SMEM, g_sp.sC>>>(
        p_ctxh, p_ctxl, p_wkvh, p_wkvl, p_dkv, 1024, (size_t)LC * CC, (size_t)LC * 1024, 0, 512);
    cudaEventRecord(g_sp.evV, g_sp.sC);
    split_kernel<<<(CC * INNER) / 256, 256, 0, g_sp.sC>>>(w_out, p_woh, p_wol, CC * INNER);
    cudaEventRecord(g_sp.evC2, g_sp.sC);

    // main: l1 half0 then half1
    cudaStreamWaitEvent(0, g_sp.evB, 0);
    l1_min_kernel<<<dim3(LC / 256, BHH / 2), 256>>>(0);
    cudaEventRecord(g_sp.evL0, 0);
    l1_min_kernel<<<dim3(LC / 256, BHH / 2), 256>>>(BHH / 2);

    // stream B: half0 selection + attention, overlapping l1(h1) on main
    cudaStreamWaitEvent(g_sp.sB, g_sp.evL0, 0);
    topk_kernel<<<BHH / 2, 1024, 0, g_sp.sB>>>(0);
    cudaStreamWaitEvent(g_sp.sB, g_sp.evV, 0);
    gather_sel<<<BHH * TK / 16, thr328, 0, g_sp.sB>>>(0);
    attn_mma<<<dim3(LQ / 128, BHH / 2), 256, 0, g_sp.sB>>>(0);
    cudaEventRecord(g_sp.evA0, g_sp.sB);

    // main: half1 selection + attention
    topk_kernel<<<BHH / 2, 1024>>>(BHH / 2);
    cudaStreamWaitEvent(0, g_sp.evV, 0);
    gather_sel<<<BHH * TK / 16, thr328>>>((BHH / 2) * TK);
    attn_mma<<<dim3(LQ / 128, BHH / 2), 256>>>(BHH / 2);

    // join + epilogue
    cudaStreamWaitEvent(0, g_sp.evA0, 0);
    cudaStreamWaitEvent(0, g_sp.evC2, 0);
    mma_bf3_gemm<<<dim3(INNER / 128, LQ / 128, BB), 256, GEMM_SMEM>>>(
        p_aoh, p_aol, p_woh, p_wol, p_dout, INNER, (size_t)LQ * INNER, (size_t)LQ * INNER, 0, 0);
    final_ln_t<<<dim3(LQ / 32, BB), thr328>>>(p_dout, on_g, on_b, qsrc, gamma, out);
}

// round 17
// speedup vs baseline: 1.0626x; 1.0626x over previous
#include <cuda_runtime.h>
#include <cuda_bf16.h>
#include <cstdint>

#define BB 2
#define CC 512
#define LQ 2048
#define LC 4096
#define HH 8
#define DD 64
#define BHH 16
#define TK 512
#define INNER 512

typedef unsigned long long ull;
typedef unsigned short u16;

// ---------------- packed f32x2 helpers ----------------
__device__ __forceinline__ void add2(ull& d, ull a, ull b) {
    asm("add.rn.f32x2 %0, %1, %2;" : "=l"(d) : "l"(a), "l"(b));
}
__device__ __forceinline__ float2 unpack2(ull v) {
    unsigned lo, hi;
    asm("mov.b64 {%0, %1}, %2;" : "=r"(lo), "=r"(hi) : "l"(v));
    return make_float2(__uint_as_float(lo), __uint_as_float(hi));
}

// ---------------- bf16 helpers ----------------
__device__ __forceinline__ u16 f2bf(float x) {
    __nv_bfloat16 b = __float2bfloat16(x);
    return *reinterpret_cast<u16*>(&b);
}
__device__ __forceinline__ float bf2f(u16 v) {
    __nv_bfloat16 b = *reinterpret_cast<__nv_bfloat16*>(&v);
    return __bfloat162float(b);
}
__device__ __forceinline__ void bsplit(float x, u16& h, u16& l) {
    h = f2bf(x);
    l = f2bf(x - bf2f(h));
}
__device__ __forceinline__ void mma_bf16(float* c, const uint32_t* a, const uint32_t* b) {
    asm volatile(
        "mma.sync.aligned.m16n8k16.row.col.f32.bf16.bf16.f32 "
        "{%0,%1,%2,%3}, {%4,%5,%6,%7}, {%8,%9}, {%0,%1,%2,%3};"
        : "+f"(c[0]), "+f"(c[1]), "+f"(c[2]), "+f"(c[3])
        : "r"(a[0]), "r"(a[1]), "r"(a[2]), "r"(a[3]), "r"(b[0]), "r"(b[1]));
}
__device__ __forceinline__ void ldsm4(uint32_t* r, uint32_t addr) {
    asm volatile("ldmatrix.sync.aligned.m8n8.x4.shared.b16 {%0,%1,%2,%3}, [%4];"
                 : "=r"(r[0]), "=r"(r[1]), "=r"(r[2]), "=r"(r[3]) : "r"(addr));
}
__device__ __forceinline__ void ldsm4t(uint32_t* r, uint32_t addr) {
    asm volatile("ldmatrix.sync.aligned.m8n8.x4.trans.shared.b16 {%0,%1,%2,%3}, [%4];"
                 : "=r"(r[0]), "=r"(r[1]), "=r"(r[2]), "=r"(r[3]) : "r"(addr));
}
__device__ __forceinline__ uint32_t smem_u32(const void* p) {
    uint32_t a;
    asm("{ .reg .u64 t; cvta.to.shared.u64 t, %1; cvt.u32.u64 %0, t; }" : "=r"(a) : "l"(p));
    return a;
}
__device__ __forceinline__ void cpa16(uint32_t s, const void* g) {
    asm volatile("cp.async.cg.shared.global [%0], [%1], 16;" :: "r"(s), "l"(g));
}

// ---------------- scratch ----------------
__device__ u16 g_ctxh[BB * LC * CC];
__device__ u16 g_ctxl[BB * LC * CC];
__device__ u16 g_qsh[BB * LQ * CC];
__device__ u16 g_qsl[BB * LQ * CC];
__device__ u16 g_wkvh[1024 * CC];
__device__ u16 g_wkvl[1024 * CC];
__device__ u16 g_wqh[INNER * CC];
__device__ u16 g_wql[INNER * CC];
__device__ u16 g_woh[CC * INNER];
__device__ u16 g_wol[CC * INNER];
__device__ u16 g_aoh[BB * LQ * INNER];
__device__ u16 g_aol[BB * LQ * INNER];
__device__ float g_dkv[BB * LC * 2 * INNER];
__device__ float g_dq[BB * LQ * INNER];
__device__ float g_dout[BB * LQ * CC];
__device__ float g_qsm[BHH * TK * DD];
__device__ float g_mind[BHH * LC];
__device__ int g_sidx[BHH * TK];
__device__ int g_uidx[BHH * TK];   // unique q indices per bh
__device__ int g_ucnt[BHH];        // unique count per bh
__device__ u16 g_kselh[BHH * TK * DD];
__device__ u16 g_ksell[BHH * TK * DD];
__device__ u16 g_vselh[BHH * TK * DD];
__device__ u16 g_vsell[BHH * TK * DD];

// ---------------- Threefry (host + device) ----------------
__host__ __device__ __forceinline__ void tf2x32(unsigned k0, unsigned k1, unsigned x0,
                                                unsigned x1, unsigned& y0, unsigned& y1) {
    unsigned ks2 = k0 ^ k1 ^ 0x1BD11BDAu;
    x0 += k0; x1 += k1;
#define TFR(r) { x0 += x1; x1 = (x1 << (r)) | (x1 >> (32 - (r))); x1 ^= x0; }
    TFR(13) TFR(15) TFR(26) TFR(6)
    x0 += k1; x1 += ks2 + 1u;
    TFR(17) TFR(29) TFR(16) TFR(24)
    x0 += ks2; x1 += k0 + 2u;
    TFR(13) TFR(15) TFR(26) TFR(6)
    x0 += k0; x1 += k1 + 3u;
    TFR(17) TFR(29) TFR(16) TFR(24)
    x0 += k1; x1 += ks2 + 4u;
    TFR(13) TFR(15) TFR(26) TFR(6)
    x0 += ks2; x1 += k0 + 5u;
#undef TFR
    y0 = x0; y1 = x1;
}

// ---------------- q-index dedup: bitmap + compaction (exact; min over set == min over multiset) ----
__global__ void dedup_kernel(unsigned k2a, unsigned k2b) {
    __shared__ unsigned bitmap[64];
    __shared__ int cnt;
    int bh = blockIdx.x, tid = threadIdx.x;
    if (tid < 64) bitmap[tid] = 0u;
    if (tid == 0) cnt = 0;
    __syncthreads();
    for (int t = tid; t < TK; t += 256) {
        unsigned y0, y1;
        tf2x32(k2a, k2b, 0u, (unsigned)(bh * TK + t), y0, y1);
        int idx = (int)((y0 ^ y1) & 2047u);
        atomicOr(&bitmap[idx >> 5], 1u << (idx & 31));
    }
    __syncthreads();
    for (int i = tid; i < 2048; i += 256) {
        if ((bitmap[i >> 5] >> (i & 31)) & 1u) {
            int p = atomicAdd(&cnt, 1);
            g_uidx[bh * TK + p] = i;
        }
    }
    __syncthreads();
    if (tid == 0) g_ucnt[bh] = cnt;
}

// ---------------- weight bf16 hi/lo split ----------------
__global__ void split_kernel(const float* __restrict__ src, u16* __restrict__ hi,
                             u16* __restrict__ lo, int n) {
    int i = blockIdx.x * 256 + threadIdx.x;
    if (i >= n) return;
    u16 h, l;
    bsplit(src[i], h, l);
    hi[i] = h;
    lo[i] = l;
}

// ---------------- ChanLN: x (b,C,L) -> bf16 hi/lo (b,L,C) ----------------
__global__ void chan_ln_t(const float* __restrict__ x, const float* __restrict__ gw,
                          const float* __restrict__ bw, u16* __restrict__ yh,
                          u16* __restrict__ yl, int L) {
    int b = blockIdx.y;
    int l0 = blockIdx.x * 32;
    int lane = threadIdx.x, wy = threadIdx.y;
    const float* xb = x + (size_t)b * CC * L;
    float s = 0.f, s2 = 0.f;
    for (int c = wy; c < CC; c += 8) {
        float v = xb[(size_t)c * L + l0 + lane];
        s += v; s2 += v * v;
    }
    __shared__ float sh_s[8][32], sh_s2[8][32];
    __shared__ float mean_s[32], rstd_s[32];
    __shared__ float tile[32][33];
    sh_s[wy][lane] = s; sh_s2[wy][lane] = s2;
    __syncthreads();
    if (wy == 0) {
        float ts = 0.f, t2 = 0.f;
        #pragma unroll
        for (int i = 0; i < 8; i++) { ts += sh_s[i][lane]; t2 += sh_s2[i][lane]; }
        float mean = ts / (float)CC;
        float var = t2 / (float)CC - mean * mean;
        mean_s[lane] = mean;
        rstd_s[lane] = rsqrtf(var + 1e-5f);
    }
    __syncthreads();
    u16* yhb = yh + (size_t)b * L * CC;
    u16* ylb = yl + (size_t)b * L * CC;
    for (int c0 = 0; c0 < CC; c0 += 32) {
        #pragma unroll
        for (int rr = 0; rr < 4; rr++) {
            int cr = wy * 4 + rr;
            tile[cr][lane] = xb[(size_t)(c0 + cr) * L + l0 + lane];
        }
        __syncthreads();
        #pragma unroll
        for (int rr = 0; rr < 4; rr++) {
            int r = wy * 4 + rr;
            int c = c0 + lane;
            float v = tile[lane][r];
            float o = (v - mean_s[r]) * rstd_s[r] * gw[c] + bw[c];
            u16 h, l;
            bsplit(o, h, l);
            yhb[(size_t)(l0 + r) * CC + c] = h;
            ylb[(size_t)(l0 + r) * CC + c] = l;
        }
        __syncthreads();
    }
}

// ---------------- final LN ----------------
__global__ void final_ln_t(const float* __restrict__ x, const float* __restrict__ gw,
                           const float* __restrict__ bw, const float* __restrict__ res,
                           const float* __restrict__ gamma, float* __restrict__ y) {
    int b = blockIdx.y;
    int l0 = blockIdx.x * 32;
    int lane = threadIdx.x, wy = threadIdx.y;
    const float* xb = x + (size_t)b * LQ * CC;
    __shared__ float mean_s[32], rstd_s[32];
    __shared__ float tile[32][33];
    #pragma unroll
    for (int rr = 0; rr < 4; rr++) {
        int r = wy * 4 + rr;
        const float* row = xb + (size_t)(l0 + r) * CC;
        float s = 0.f, s2 = 0.f;
        for (int c = lane; c < CC; c += 32) { float v = row[c]; s += v; s2 += v * v; }
        #pragma unroll
        for (int o = 16; o > 0; o >>= 1) {
            s += __shfl_xor_sync(0xFFFFFFFFu, s, o);
            s2 += __shfl_xor_sync(0xFFFFFFFFu, s2, o);
        }
        if (lane == 0) {
            float mean = s / (float)CC;
            float var = s2 / (float)CC - mean * mean;
            mean_s[r] = mean;
            rstd_s[r] = rsqrtf(var + 1e-5f);
        }
    }
    __syncthreads();
    float gm = gamma[0];
    const float* rb = res + (size_t)b * CC * LQ;
    float* yb = y + (size_t)b * CC * LQ;
    for (int c0 = 0; c0 < CC; c0 += 32) {
        #pragma unroll
        for (int rr = 0; rr < 4; rr++) {
            int r = wy * 4 + rr;
            tile[r][lane] = xb[(size_t)(l0 + r) * CC + c0 + lane];
        }
        __syncthreads();
        #pragma unroll
        for (int rr = 0; rr < 4; rr++) {
            int cr = wy * 4 + rr;
            int c = c0 + cr;
            float v = tile[lane][cr];
            float o = gm * ((v - mean_s[lane]) * rstd_s[lane] * gw[c] + bw[c])
                      + rb[(size_t)c * LQ + l0 + lane];
            yb[(size_t)c * LQ + l0 + lane] = o;
        }
        __syncthreads();
    }
}

// ---------------- pipelined 3xBF16 GEMM (ldmatrix frags) + fused L2-norm epilogue ----------------
#define KCW 32
#define LDAU 20
#define TSZ (128 * LDAU)
__global__ void __launch_bounds__(256, 2) mma_bf3_gemm(const u16* __restrict__ Xh,
                                                       const u16* __restrict__ Xl,
                                                       const u16* __restrict__ Wh,
                                                       const u16* __restrict__ Wl,
                                                       float* __restrict__ Dout, int Ncols,
                                                       size_t xStride, size_t dStride,
                                                       int normMode, int bnOff) {
    extern __shared__ uint32_t sm[];
    uint32_t* Ah = sm;
    uint32_t* Al = sm + 2 * TSZ;
    uint32_t* Bh = sm + 4 * TSZ;
    uint32_t* Bl = sm + 6 * TSZ;
    int tid = threadIdx.x;
    int warp = tid >> 5, lane = tid & 31;
    int wm = warp & 1, wn = warp >> 1;
    int g = lane >> 2, t = lane & 3;
    int bn = blockIdx.x * 128 + bnOff, bm = blockIdx.y * 128, b = blockIdx.z;
    const u16* Xbh = Xh + (size_t)b * xStride;
    const u16* Xbl = Xl + (size_t)b * xStride;
    float* Db = Dout + (size_t)b * dStride;
    int emode = (normMode == 1 && bn >= 512) ? 0 : normMode;

    float acc[4][4][4];
    #pragma unroll
    for (int i = 0; i < 4; i++)
        #pragma unroll
        for (int j = 0; j < 4; j++)
            #pragma unroll
            for (int e = 0; e < 4; e++) acc[i][j][e] = 0.f;

    int lrow = tid >> 2;
    int lchk = tid & 3;

    auto load_stage = [&](int buf, int k0) {
        #pragma unroll
        for (int p = 0; p < 2; p++) {
            int row = p * 64 + lrow;
            size_t go = (size_t)(bm + row) * CC + k0 + lchk * 8;
            size_t gw = (size_t)(bn + row) * CC + k0 + lchk * 8;
            uint32_t so = (uint32_t)(buf * TSZ + row * LDAU + lchk * 4) * 4u;
            cpa16(smem_u32(Ah) + so, Xbh + go);
            cpa16(smem_u32(Al) + so, Xbl + go);
            cpa16(smem_u32(Bh) + so, Wh + gw);
            cpa16(smem_u32(Bl) + so, Wl + gw);
        }
        asm volatile("cp.async.commit_group;" ::: "memory");
    };

    int lsel = lane & 15, khalf = lane >> 4;
    uint32_t aoff[4];
    #pragma unroll
    for (int mt = 0; mt < 4; mt++)
        aoff[mt] = (uint32_t)(((wm * 64 + mt * 16 + lsel) * LDAU + khalf * 4) * 4);
    int bseg = lane >> 3, brow = lane & 7;
    uint32_t boff[2];
    #pragma unroll
    for (int np = 0; np < 2; np++)
        boff[np] = (uint32_t)(((wn * 32 + (np * 2 + (bseg >> 1)) * 8 + brow) * LDAU
                               + (bseg & 1) * 4) * 4);
    uint32_t aBaseH = smem_u32(Ah), aBaseL = smem_u32(Al);
    uint32_t bBaseH = smem_u32(Bh), bBaseL = smem_u32(Bl);

    const int NST = CC / KCW;
    load_stage(0, 0);
    for (int st = 0; st < NST; st++) {
        if (st + 1 < NST) {
            load_stage((st + 1) & 1, (st + 1) * KCW);
            asm volatile("cp.async.wait_group 1;" ::: "memory");
        } else {
            asm volatile("cp.async.wait_group 0;" ::: "memory");
        }
        __syncthreads();
        int buf = st & 1;
        #pragma unroll
        for (int ks = 0; ks < 2; ks++) {
            uint32_t kso = (uint32_t)((buf * TSZ + ks * 8) * 4);
            uint32_t bh4[2][4], bl4[2][4];
            ldsm4(bh4[0], bBaseH + boff[0] + kso);
            ldsm4(bh4[1], bBaseH + boff[1] + kso);
            ldsm4(bl4[0], bBaseL + boff[0] + kso);
            ldsm4(bl4[1], bBaseL + boff[1] + kso);
            #pragma unroll
            for (int mt = 0; mt < 4; mt++) {
                uint32_t ah[4], al[4];
                ldsm4(ah, aBaseH + aoff[mt] + kso);
                ldsm4(al, aBaseL + aoff[mt] + kso);
                #pragma unroll
                for (int nt = 0; nt < 4; nt++) {
                    uint32_t bhi[2] = {bh4[nt >> 1][(nt & 1) * 2], bh4[nt >> 1][(nt & 1) * 2 + 1]};
                    uint32_t blo[2] = {bl4[nt >> 1][(nt & 1) * 2], bl4[nt >> 1][(nt & 1) * 2 + 1]};
                    mma_bf16(acc[mt][nt], ah, bhi);
                    mma_bf16(acc[mt][nt], ah, blo);
                    mma_bf16(acc[mt][nt], al, bhi);
                }
            }
        }
        __syncthreads();
    }

    float* ns = reinterpret_cast<float*>(sm);
    int hh = wn >> 1;
    if (emode != 0) {
        for (int i = tid; i < 256; i += 256) ns[i] = 0.f;
        __syncthreads();
        #pragma unroll
        for (int mt = 0; mt < 4; mt++) {
            float p0 = 0.f, p1 = 0.f;
            #pragma unroll
            for (int nt = 0; nt < 4; nt++) {
                p0 += acc[mt][nt][0] * acc[mt][nt][0] + acc[mt][nt][1] * acc[mt][nt][1];
                p1 += acc[mt][nt][2] * acc[mt][nt][2] + acc[mt][nt][3] * acc[mt][nt][3];
            }
            int r0 = wm * 64 + mt * 16 + g;
            atomicAdd(&ns[r0 * 2 + hh], p0);
            atomicAdd(&ns[(r0 + 8) * 2 + hh], p1);
        }
        __syncthreads();
    }
    bool donorm = (emode == 2) || (emode == 1 && (bn + wn * 32) < 512);
    #pragma unroll
    for (int mt = 0; mt < 4; mt++) {
        int rl = wm * 64 + mt * 16 + g;
        float inv0 = 1.f, inv1 = 1.f;
        if (donorm) {
            inv0 = 1.f / fmaxf(sqrtf(ns[rl * 2 + hh]), 1e-12f);
            inv1 = 1.f / fmaxf(sqrtf(ns[(rl + 8) * 2 + hh]), 1e-12f);
        }
        int r0 = bm + rl;
        #pragma unroll
        for (int nt = 0; nt < 4; nt++) {
            int c0 = bn + wn * 32 + nt * 8 + t * 2;
            *reinterpret_cast<float2*>(&Db[(size_t)r0 * Ncols + c0]) =
                make_float2(acc[mt][nt][0] * inv0, acc[mt][nt][1] * inv0);
            *reinterpret_cast<float2*>(&Db[(size_t)(r0 + 8) * Ncols + c0]) =
                make_float2(acc[mt][nt][2] * inv1, acc[mt][nt][3] * inv1);
        }
    }
}

// ---------------- gathers ----------------
// gather unique q rows (count per bh in g_ucnt)
__global__ void gather_qsmall() {
    int r = blockIdx.x * 8 + threadIdx.y;
    int bh = r >> 9;
    int t = r & (TK - 1);
    if (t >= g_ucnt[bh]) return;
    int b = bh >> 3, h = bh & 7;
    int idx = g_uidx[r];
    const float* s = g_dq + ((size_t)b * LQ + idx) * INNER + h * DD;
    float* d = g_qsm + (size_t)r * DD;
    d[threadIdx.x] = s[threadIdx.x];
    d[threadIdx.x + 32] = s[threadIdx.x + 32];
}

// gather selected K and V as bf16 hi/lo
__global__ void gather_sel() {
    int r = blockIdx.x * 8 + threadIdx.y;
    int bh = r >> 9;
    int b = bh >> 3, h = bh & 7;
    int idx = g_sidx[r];
    const float* ks = g_dkv + ((size_t)b * LC + idx) * (2 * INNER) + h * DD;
    #pragma unroll
    for (int p = 0; p < 2; p++) {
        int c = threadIdx.x + p * 32;
        u16 hh_, ll_;
        bsplit(ks[c], hh_, ll_);
        g_kselh[(size_t)r * DD + c] = hh_;
        g_ksell[(size_t)r * DD + c] = ll_;
        bsplit(ks[INNER + c], hh_, ll_);
        g_vselh[(size_t)r * DD + c] = hh_;
        g_vsell[(size_t)r * DD + c] = ll_;
    }
}

// ---------------- L1 min-distance over unique q (runtime tail tile) ----------------
__global__ void __launch_bounds__(256, 2) l1_min_kernel() {
    int bh = blockIdx.y;
    int b = bh >> 3, h = bh & 7;
    int kl = blockIdx.x * 256 + threadIdx.x;
    const ull* kp = reinterpret_cast<const ull*>(g_dkv + ((size_t)b * LC + kl) * (2 * INNER) + h * DD);
    ull kr2[32];
    #pragma unroll
    for (int i = 0; i < 32; i++) kr2[i] = kp[i];
    __shared__ float qs[128 * 64];
    const ull ABSM = 0x7FFFFFFF7FFFFFFFull;
    int cnt = g_ucnt[bh];
    float best = 3.4e38f;
    for (int qc = 0; qc < cnt; qc += 128) {
        int lim = min(128, cnt - qc);
        const float4* qsrc4 = reinterpret_cast<const float4*>(g_qsm + ((size_t)bh * TK + qc) * DD);
        for (int j = threadIdx.x; j < lim * 16; j += 256) {
            float4 v = qsrc4[j];
            reinterpret_cast<float4*>(qs)[j] = make_float4(-v.x, -v.y, -v.z, -v.w);
        }
        __syncthreads();
        for (int qq = 0; qq < lim; qq++) {
            const ull* qp = reinterpret_cast<const ull*>(qs + qq * 64);
            ull a0 = 0ull, a1 = 0ull, a2 = 0ull, a3 = 0ull;
            #pragma unroll
            for (int i = 0; i < 32; i += 4) {
                ull d0, d1, d2, d3;
                add2(d0, kr2[i + 0], qp[i + 0]); d0 &= ABSM; add2(a0, a0, d0);
                add2(d1, kr2[i + 1], qp[i + 1]); d1 &= ABSM; add2(a1, a1, d1);
                add2(d2, kr2[i + 2], qp[i + 2]); d2 &= ABSM; add2(a2, a2, d2);
                add2(d3, kr2[i + 3], qp[i + 3]); d3 &= ABSM; add2(a3, a3, d3);
            }
            ull s01, s23, s;
            add2(s01, a0, a1);
            add2(s23, a2, a3);
            add2(s, s01, s23);
            float2 f = unpack2(s);
            best = fminf(best, f.x + f.y);
        }
        __syncthreads();
    }
    g_mind[(size_t)bh * LC + kl] = best;
}

// ---------------- top-512 smallest via bitonic sort ----------------
__global__ void __launch_bounds__(1024) topk_kernel() {
    __shared__ ull keys[LC];
    int bh = blockIdx.x;
    int tid = threadIdx.x;
    for (int i = tid; i < LC; i += 1024) {
        unsigned fb = __float_as_uint(g_mind[(size_t)bh * LC + i]);
        keys[i] = ((ull)fb << 32) | (unsigned)i;
    }
    __syncthreads();
    for (int k = 2; k <= LC; k <<= 1) {
        for (int j = k >> 1; j > 0; j >>= 1) {
            for (int i = tid; i < LC; i += 1024) {
                int ixj = i ^ j;
                if (ixj > i) {
                    ull a = keys[i], bb = keys[ixj];
                    bool up = ((i & k) == 0);
                    if ((a > bb) == up) { keys[i] = bb; keys[ixj] = a; }
                }
            }
            __syncthreads();
        }
    }
    for (int i = tid; i < TK; i += 1024)
        g_sidx[bh * TK + i] = (int)(keys[i] & 0xFFFFFFFFu);
}

// ---------------- flash attention on bf16 mma (full hi/lo on S, P, V) ----------------
#define LDS2 72
__global__ void __launch_bounds__(256) attn_mma() {
    __shared__ u16 smA[128 * LDS2];
    __shared__ u16 smB[128 * LDS2];
    int bh = blockIdx.y;
    int b = bh >> 3, h = bh & 7;
    int bm = blockIdx.x * 128;
    int tid = threadIdx.x, w = tid >> 5, lane = tid & 31;
    int g = lane >> 2, t = lane & 3;

    for (int i = tid; i < 128 * 64; i += 256) {
        int row = i >> 6, c = i & 63;
        float v = g_dq[((size_t)b * LQ + bm + row) * INNER + h * DD + c];
        u16 hh_, ll_;
        bsplit(v, hh_, ll_);
        smA[row * LDS2 + c] = hh_;
        smB[row * LDS2 + c] = ll_;
    }
    __syncthreads();

    uint32_t qh[4][4], ql[4][4];
    int arow = lane & 15, ahalf = lane >> 4;
    #pragma unroll
    for (int ks = 0; ks < 4; ks++) {
        ldsm4(qh[ks], smem_u32(&smA[(w * 16 + arow) * LDS2 + ks * 16 + ahalf * 8]));
        ldsm4(ql[ks], smem_u32(&smB[(w * 16 + arow) * LDS2 + ks * 16 + ahalf * 8]));
    }
    __syncthreads();

    u16* Kh = smA;
    u16* Kl = smA + 64 * LDS2;
    u16* Vh = smB;
    u16* Vl = smB + 64 * LDS2;

    float O[8][4];
    #pragma unroll
    for (int i = 0; i < 8; i++)
        #pragma unroll
        for (int e = 0; e < 4; e++) O[i][e] = 0.f;
    float den0 = 0.f, den1 = 0.f;

    int brow = ((lane >> 4) << 3) + (lane & 7);
    int bhalf = (lane >> 3) & 1;
    int vrow = ((lane >> 3) & 1) * 8 + (lane & 7);
    int vch = lane >> 4;

    for (int kc = 0; kc < TK; kc += 64) {
        for (int j = tid; j < 512; j += 256) {
            int row = j >> 3, seg = j & 7;
            size_t src = ((size_t)bh * TK + kc + row) * DD + seg * 8;
            uint32_t dst = (uint32_t)(row * LDS2 + seg * 8) * 2u;
            cpa16(smem_u32(Kh) + dst, g_kselh + src);
            cpa16(smem_u32(Kl) + dst, g_ksell + src);
            cpa16(smem_u32(Vh) + dst, g_vselh + src);
            cpa16(smem_u32(Vl) + dst, g_vsell + src);
        }
        asm volatile("cp.async.commit_group;" ::: "memory");
        asm volatile("cp.async.wait_group 0;" ::: "memory");
        __syncthreads();

        float S[8][4];
        #pragma unroll
        for (int i = 0; i < 8; i++)
            #pragma unroll
            for (int e = 0; e < 4; e++) S[i][e] = 0.f;
        #pragma unroll
        for (int ks = 0; ks < 4; ks++) {
            #pragma unroll
            for (int pr = 0; pr < 4; pr++) {
                uint32_t kh4[4], kl4[4];
                uint32_t ko = (uint32_t)((pr * 16 + brow) * LDS2 + ks * 16 + bhalf * 8) * 2u;
                ldsm4(kh4, smem_u32(Kh) + ko);
                ldsm4(kl4, smem_u32(Kl) + ko);
                #pragma unroll
                for (int sub = 0; sub < 2; sub++) {
                    int nt = pr * 2 + sub;
                    uint32_t bhr[2] = {kh4[sub * 2], kh4[sub * 2 + 1]};
                    uint32_t blr[2] = {kl4[sub * 2], kl4[sub * 2 + 1]};
                    mma_bf16(S[nt], qh[ks], bhr);
                    mma_bf16(S[nt], qh[ks], blr);
                    mma_bf16(S[nt], ql[ks], bhr);
                }
            }
        }

        #pragma unroll
        for (int ks = 0; ks < 4; ks++) {
            uint32_t prh[4], prl[4];
            #pragma unroll
            for (int half = 0; half < 2; half++) {
                int nt = 2 * ks + half;
                #pragma unroll
                for (int pe = 0; pe < 2; pe++) {
                    float w0 = __expf(S[nt][pe * 2]);
                    float w1 = __expf(S[nt][pe * 2 + 1]);
                    u16 h0, l0, h1, l1;
                    bsplit(w0, h0, l0);
                    bsplit(w1, h1, l1);
                    prh[half * 2 + pe] = (uint32_t)h0 | ((uint32_t)h1 << 16);
                    prl[half * 2 + pe] = (uint32_t)l0 | ((uint32_t)l1 << 16);
                    float wr0 = bf2f(h0) + bf2f(l0);
                    float wr1 = bf2f(h1) + bf2f(l1);
                    if (pe == 0) den0 += wr0 + wr1; else den1 += wr0 + wr1;
                }
            }
            #pragma unroll
            for (int vp = 0; vp < 4; vp++) {
                uint32_t vh4[4], vl4[4];
                uint32_t vo = (uint32_t)((ks * 16 + vrow) * LDS2 + vp * 16 + vch * 8) * 2u;
                ldsm4t(vh4, smem_u32(Vh) + vo);
                ldsm4t(vl4, smem_u32(Vl) + vo);
                #pragma unroll
                for (int sub = 0; sub < 2; sub++) {
                    uint32_t vbh[2] = {vh4[sub * 2], vh4[sub * 2 + 1]};
                    uint32_t vbl[2] = {vl4[sub * 2], vl4[sub * 2 + 1]};
                    mma_bf16(O[vp * 2 + sub], prh, vbh);
                    mma_bf16(O[vp * 2 + sub], prh, vbl);
                    mma_bf16(O[vp * 2 + sub], prl, vbh);
                }
            }
        }
        __syncthreads();
    }

    den0 += __shfl_xor_sync(0xFFFFFFFFu, den0, 1);
    den0 += __shfl_xor_sync(0xFFFFFFFFu, den0, 2);
    den1 += __shfl_xor_sync(0xFFFFFFFFu, den1, 1);
    den1 += __shfl_xor_sync(0xFFFFFFFFu, den1, 2);
    float inv0 = 1.f / den0, inv1 = 1.f / den1;

    int row0 = bm + w * 16 + g;
    #pragma unroll
    for (int nt = 0; nt < 8; nt++) {
        int col = h * DD + nt * 8 + t * 2;
        float o0 = O[nt][0] * inv0, o1 = O[nt][1] * inv0;
        float o2 = O[nt][2] * inv1, o3 = O[nt][3] * inv1;
        u16 h0, l0, h1, l1, h2, l2, h3, l3;
        bsplit(o0, h0, l0); bsplit(o1, h1, l1);
        bsplit(o2, h2, l2); bsplit(o3, h3, l3);
        size_t i0 = ((size_t)b * LQ + row0) * INNER + col;
        size_t i1 = ((size_t)b * LQ + row0 + 8) * INNER + col;
        *reinterpret_cast<uint32_t*>(g_aoh + i0) = (uint32_t)h0 | ((uint32_t)h1 << 16);
        *reinterpret_cast<uint32_t*>(g_aol + i0) = (uint32_t)l0 | ((uint32_t)l1 << 16);
        *reinterpret_cast<uint32_t*>(g_aoh + i1) = (uint32_t)h2 | ((uint32_t)h3 << 16);
        *reinterpret_cast<uint32_t*>(g_aol + i1) = (uint32_t)l2 | ((uint32_t)l3 << 16);
    }
}

// ---------------- streams/events (static init; no device memory) ----------------
struct StreamPack {
    cudaStream_t sB, sC;
    cudaEvent_t evRoot, evB, evC, evC2;
    StreamPack() {
        cudaStreamCreateWithFlags(&sB, cudaStreamNonBlocking);
        cudaStreamCreateWithFlags(&sC, cudaStreamNonBlocking);
        cudaEventCreateWithFlags(&evRoot, cudaEventDisableTiming);
        cudaEventCreateWithFlags(&evB, cudaEventDisableTiming);
        cudaEventCreateWithFlags(&evC, cudaEventDisableTiming);
        cudaEventCreateWithFlags(&evC2, cudaEventDisableTiming);
    }
};
static StreamPack g_sp;

// ---------------- host ----------------
extern "C" void kernel_launch(void* const* d_in, const int* in_sizes, int n_in,
                              void* d_out, int out_size) {
    (void)in_sizes; (void)n_in; (void)out_size;
    const float* qsrc  = (const float*)d_in[0];
    const float* ctx   = (const float*)d_in[1];
    const float* cn_g  = (const float*)d_in[2];
    const float* cn_b  = (const float*)d_in[3];
    const float* qn_g  = (const float*)d_in[4];
    const float* qn_b  = (const float*)d_in[5];
    const float* on_g  = (const float*)d_in[6];
    const float* on_b  = (const float*)d_in[7];
    const float* w_kv  = (const float*)d_in[8];
    const float* w_q   = (const float*)d_in[9];
    const float* w_out = (const float*)d_in[10];
    const float* gamma = (const float*)d_in[11];
    float* out = (float*)d_out;

    u16 *p_ctxh, *p_ctxl, *p_qsh, *p_qsl, *p_wkvh, *p_wkvl, *p_wqh, *p_wql,
        *p_woh, *p_wol, *p_aoh, *p_aol;
    float *p_dkv, *p_dq, *p_dout;
    cudaGetSymbolAddress((void**)&p_ctxh, g_ctxh);
    cudaGetSymbolAddress((void**)&p_ctxl, g_ctxl);
    cudaGetSymbolAddress((void**)&p_qsh, g_qsh);
    cudaGetSymbolAddress((void**)&p_qsl, g_qsl);
    cudaGetSymbolAddress((void**)&p_wkvh, g_wkvh);
    cudaGetSymbolAddress((void**)&p_wkvl, g_wkvl);
    cudaGetSymbolAddress((void**)&p_wqh, g_wqh);
    cudaGetSymbolAddress((void**)&p_wql, g_wql);
    cudaGetSymbolAddress((void**)&p_woh, g_woh);
    cudaGetSymbolAddress((void**)&p_wol, g_wol);
    cudaGetSymbolAddress((void**)&p_aoh, g_aoh);
    cudaGetSymbolAddress((void**)&p_aol, g_aol);
    cudaGetSymbolAddress((void**)&p_dkv, g_dkv);
    cudaGetSymbolAddress((void**)&p_dq, g_dq);
    cudaGetSymbolAddress((void**)&p_dout, g_dout);

    unsigned k2a, k2b;
    tf2x32(0u, 42u, 0u, 1u, k2a, k2b);

    const int GEMM_SMEM = 8 * TSZ * 4;  // 81920 bytes -> 2 CTAs/SM
    cudaFuncSetAttribute(mma_bf3_gemm, cudaFuncAttributeMaxDynamicSharedMemorySize, GEMM_SMEM);

    dim3 thr328(32, 8);

    // ---- fork (R14 schedule + dedup on B) ----
    cudaEventRecord(g_sp.evRoot, 0);
    cudaStreamWaitEvent(g_sp.sB, g_sp.evRoot, 0);
    cudaStreamWaitEvent(g_sp.sC, g_sp.evRoot, 0);

    // stream C: weight splits
    split_kernel<<<(1024 * CC) / 256, 256, 0, g_sp.sC>>>(w_kv, p_wkvh, p_wkvl, 1024 * CC);
    cudaEventRecord(g_sp.evC, g_sp.sC);
    split_kernel<<<(CC * INNER) / 256, 256, 0, g_sp.sC>>>(w_out, p_woh, p_wol, CC * INNER);
    cudaEventRecord(g_sp.evC2, g_sp.sC);

    // stream B: dedup -> q path (LN -> split -> GEMM -> unique-q gather)
    dedup_kernel<<<BHH, 256, 0, g_sp.sB>>>(k2a, k2b);
    chan_ln_t<<<dim3(LQ / 32, BB), thr328, 0, g_sp.sB>>>(qsrc, qn_g, qn_b, p_qsh, p_qsl, LQ);
    split_kernel<<<(INNER * CC) / 256, 256, 0, g_sp.sB>>>(w_q, p_wqh, p_wql, INNER * CC);
    mma_bf3_gemm<<<dim3(INNER / 128, LQ / 128, BB), 256, GEMM_SMEM, g_sp.sB>>>(
        p_qsh, p_qsl, p_wqh, p_wql, p_dq, INNER, (size_t)LQ * CC, (size_t)LQ * INNER, 2, 0);
    gather_qsmall<<<BHH * TK / 8, thr328, 0, g_sp.sB>>>();
    cudaEventRecord(g_sp.evB, g_sp.sB);

    // main: ctx LN -> kv GEMM -> selection chain -> attention -> out GEMM -> final LN
    chan_ln_t<<<dim3(LC / 32, BB), thr328>>>(ctx, cn_g, cn_b, p_ctxh, p_ctxl, LC);
    cudaStreamWaitEvent(0, g_sp.evC, 0);
    mma_bf3_gemm<<<dim3(1024 / 128, LC / 128, BB), 256, GEMM_SMEM>>>(
        p_ctxh, p_ctxl, p_wkvh, p_wkvl, p_dkv, 1024, (size_t)LC * CC, (size_t)LC * 1024, 1, 0);
    cudaStreamWaitEvent(0, g_sp.evB, 0);
    l1_min_kernel<<<dim3(LC / 256, BHH), 256>>>();
    topk_kernel<<<BHH, 1024>>>();
    gather_sel<<<BHH * TK / 8, thr328>>>();
    attn_mma<<<dim3(LQ / 128, BHH), 256>>>();
    cudaStreamWaitEvent(0, g_sp.evC2, 0);
    mma_bf3_gemm<<<dim3(INNER / 128, LQ / 128, BB), 256, GEMM_SMEM>>>(
        p_aoh, p_aol, p_woh, p_wol, p_dout, INNER, (size_t)LQ * INNER, (size_t)LQ * INNER, 0, 0);
    final_ln_t<<<dim3(LQ / 32, BB), thr328>>>(p_dout, on_g, on_b, qsrc, gamma, out);
}